// round 16
// baseline (speedup 1.0000x reference)
#include <cuda_runtime.h>
#include <math.h>

#define Bz 8
#define Sz 8192
#define Hz 128
#define STEPS 20
#define NBPB 16              // blocks per batch
#define NB (Bz * NBPB)       // 128 blocks (<=148 SMs -> co-resident)
#define NT 1024              // 32 warps/block
#define SCHUNK 512           // positions per block

typedef unsigned long long ull;

// -------- persistent scratch --------
__device__ float  g_coef[4 * Hz];   // a0 | a1 | dd | C
__device__ float2 g_U[4 * Hz];      // W_ih @ W_dec
__device__ float  g_V[4 * Hz];      // W_ih @ b_dec + b_ih + b_hh
__device__ __align__(16) float4 g_pg4[2][Bz][Hz];     // gate partials {i,f,c,o}
__device__ __align__(16) float4 g_part2[2][Bz][NBPB]; // {m, id-bits, ssum, tag}
__device__ int      g_bmax[Bz];
__device__ int      g_dnz[Bz];
__device__ unsigned g_bcnt[Bz];
__device__ unsigned g_bgen[Bz];

// -------- batch-local barrier (init / teardown only) --------
__device__ __forceinline__ void batch_barrier(int b) {
    __syncthreads();
    if (threadIdx.x == 0) {
        unsigned gen;
        asm volatile("ld.acquire.gpu.global.u32 %0, [%1];"
                     : "=r"(gen) : "l"(&g_bgen[b]) : "memory");
        unsigned arrived;
        asm volatile("atom.acq_rel.gpu.global.add.u32 %0, [%1], %2;"
                     : "=r"(arrived) : "l"(&g_bcnt[b]), "r"(1u) : "memory");
        if (arrived == NBPB - 1) {
            asm volatile("st.global.u32 [%0], %1;" :: "l"(&g_bcnt[b]), "r"(0u) : "memory");
            asm volatile("st.release.gpu.global.u32 [%0], %1;"
                         :: "l"(&g_bgen[b]), "r"(gen + 1u) : "memory");
        } else {
            unsigned cur;
            do {
                asm volatile("ld.acquire.gpu.global.u32 %0, [%1];"
                             : "=r"(cur) : "l"(&g_bgen[b]) : "memory");
            } while (cur == gen);
        }
    }
    __syncthreads();
}

// -------- packed f32x2 helpers --------
__device__ __forceinline__ ull f2add(ull a, ull b) {
    ull d; asm("add.rn.f32x2 %0, %1, %2;" : "=l"(d) : "l"(a), "l"(b)); return d;
}
__device__ __forceinline__ ull f2mul(ull a, ull b) {
    ull d; asm("mul.rn.f32x2 %0, %1, %2;" : "=l"(d) : "l"(a), "l"(b)); return d;
}
__device__ __forceinline__ ull f2fma(ull a, ull b, ull c) {
    ull d; asm("fma.rn.f32x2 %0, %1, %2, %3;" : "=l"(d) : "l"(a), "l"(b), "l"(c)); return d;
}
__device__ __forceinline__ ull dup2(float f) {
    ull d; asm("mov.b64 %0, {%1, %2};" : "=l"(d) : "f"(f), "f"(f)); return d;
}
__device__ __forceinline__ ull pack2(float lo, float hi) {
    ull d; asm("mov.b64 %0, {%1, %2};" : "=l"(d) : "f"(lo), "f"(hi)); return d;
}
__device__ __forceinline__ void unpack2(ull v, float& lo, float& hi) {
    asm("mov.b64 {%0, %1}, %2;" : "=f"(lo), "=f"(hi) : "l"(v));
}

// tanh Taylor tail: NC=3 deg-7 (|x|<=0.23), NC=4 deg-9 (|x|<=0.32), NC=6 deg-13 (|x|<=0.55)
template<int NC>
__device__ __forceinline__ ull poly_core(ull X, ull wd, ull A) {
    const ull C1 = dup2(-0.33333334f);
    const ull C2 = dup2( 0.13333334f);
    const ull C3 = dup2(-0.053968254f);
    const ull C4 = dup2( 0.021869489f);
    const ull C5 = dup2(-0.008863236f);
    const ull C6 = dup2( 0.0035921280f);
    const ull ONE = dup2(1.0f);
    ull Y = f2mul(X, X);
    ull P;
    if (NC == 6) {
        P = f2fma(Y, C6, C5);
        P = f2fma(P, Y, C4);
        P = f2fma(P, Y, C3);
        P = f2fma(P, Y, C2);
    } else if (NC == 4) {
        P = f2fma(Y, C4, C3);
        P = f2fma(P, Y, C2);
    } else {
        P = f2fma(Y, C3, C2);
    }
    P = f2fma(P, Y, C1);
    P = f2fma(P, Y, ONE);
    return f2fma(wd, f2mul(X, P), A);
}

// 16 rows x 4 positions per thread; one LDS.128 per row; ALU dup expansion
template<int NC, bool HASD>
__device__ __forceinline__ void scan16b(int g0,
                                        ull XV0, ull XV1, ull YV0, ull YV1,
                                        ull DV0, ull DV1,
                                        const float4* __restrict__ s_tab4,
                                        const float* __restrict__ s_ddt,
                                        ull& A0, ull& A1) {
    #pragma unroll
    for (int i = 0; i < 16; ++i) {
        int g = g0 + i;
        float4 v = s_tab4[g];                 // {a0, a1, q+C, w}
        ull a0d = dup2(v.x), a1d = dup2(v.y);
        ull qd  = dup2(v.z), wd  = dup2(v.w);
        ull X0 = f2fma(a1d, YV0, qd);
        ull X1 = f2fma(a1d, YV1, qd);
        X0 = f2fma(a0d, XV0, X0);
        X1 = f2fma(a0d, XV1, X1);
        if (HASD) {
            ull ddd = dup2(s_ddt[g]);
            X0 = f2fma(ddd, DV0, X0);
            X1 = f2fma(ddd, DV1, X1);
        }
        A0 = poly_core<NC>(X0, wd, A0);
        A1 = poly_core<NC>(X1, wd, A1);
    }
}

__device__ __forceinline__ float sigmoidf(float x) { return 1.f / (1.f + expf(-x)); }

#define SMAX_COMBINE(m, id, ss, mo, io, so)                          \
    if ((mo) > (m) || ((mo) == (m) && (io) < (id))) {                \
        (ss) = (ss) * __expf((m) - (mo)) + (so);                     \
        (m) = (mo); (id) = (io);                                     \
    } else {                                                         \
        (ss) = (ss) + (so) * __expf((mo) - (m));                     \
    }

// -------- K0: coalesced fold --------
__global__ void coef_kernel(const float* __restrict__ W_ref, const float* __restrict__ W_s,
                            const float* __restrict__ b_s,   const float* __restrict__ b_ref,
                            const float* __restrict__ W_pd,  const float* __restrict__ W_d,
                            const float* __restrict__ b_d,   const float* __restrict__ b_pd,
                            const float* __restrict__ W_ih,  const float* __restrict__ W_dec,
                            const float* __restrict__ b_dec, const float* __restrict__ b_ih,
                            const float* __restrict__ b_hh) {
    __shared__ float s_r[4][4];
    const int h = threadIdx.x, w = h >> 5, l = h & 31;
    float v0, v1, v2, v3;
    if (blockIdx.x < 512) {
        int j = blockIdx.x;
        float wij = W_ih[j * Hz + h];
        v0 = wij * W_dec[h * 2 + 0];
        v1 = wij * W_dec[h * 2 + 1];
        v2 = wij * b_dec[h];
        v3 = 0.f;
    } else {
        int g = blockIdx.x - 512;
        float wr = W_ref[g * Hz + h];
        float wp = W_pd[g * Hz + h];
        v0 = wr * W_s[h * 2 + 0];
        v1 = wr * W_s[h * 2 + 1];
        v2 = fmaf(wr, b_s[h], wp * b_d[h]);
        v3 = wp * W_d[h];
    }
    #pragma unroll
    for (int off = 16; off > 0; off >>= 1) {
        v0 += __shfl_down_sync(0xffffffffu, v0, off);
        v1 += __shfl_down_sync(0xffffffffu, v1, off);
        v2 += __shfl_down_sync(0xffffffffu, v2, off);
        v3 += __shfl_down_sync(0xffffffffu, v3, off);
    }
    if (l == 0) { s_r[0][w] = v0; s_r[1][w] = v1; s_r[2][w] = v2; s_r[3][w] = v3; }
    __syncthreads();
    if (h == 0) {
        float r0 = s_r[0][0] + s_r[0][1] + s_r[0][2] + s_r[0][3];
        float r1 = s_r[1][0] + s_r[1][1] + s_r[1][2] + s_r[1][3];
        float r2 = s_r[2][0] + s_r[2][1] + s_r[2][2] + s_r[2][3];
        float r3 = s_r[3][0] + s_r[3][1] + s_r[3][2] + s_r[3][3];
        if (blockIdx.x < 512) {
            int j = blockIdx.x;
            g_U[j] = make_float2(r0, r1);
            g_V[j] = r2 + b_ih[j] + b_hh[j];
        } else {
            int g = blockIdx.x - 512;
            g_coef[g] = r0;
            g_coef[Hz + g] = r1;
            g_coef[2 * Hz + g] = r3;
            g_coef[3 * Hz + g] = r2 + b_ref[g] + b_pd[g];
        }
    }
}

// -------- persistent decode kernel --------
__global__ __launch_bounds__(NT, 1)
void persist_kernel(const float* __restrict__ st,  const float* __restrict__ dyn,
                    const float* __restrict__ W_hh, const float* __restrict__ W_q,
                    const float* __restrict__ b_q,  const float* __restrict__ W_att,
                    float* __restrict__ out, int out_size) {
    const int blk = blockIdx.x;
    const int b = blk / NBPB;
    const int k = blk % NBPB;
    const int t = threadIdx.x;
    const int w = t >> 5, l = t & 31;
    const int pg = t & 127, rg = t >> 7;

    extern __shared__ float dsm[];
    float* s_wq = dsm;                                   // 64 KB
    ulonglong2* s_acc = (ulonglong2*)(dsm + Hz * Hz);    // 16 KB

    __shared__ float s_whh[32 * Hz];                     // 16 KB
    __shared__ __align__(16) float4 s_uvv[4 * Hz];       // 8 KB
    __shared__ __align__(16) float4 s_tab4[Hz];
    __shared__ __align__(16) float s_wm32[16];           // per-warp |qc| maxima
    __shared__ float s_a0[Hz], s_a1[Hz], s_dd[Hz], s_w[Hz], s_Cg[Hz], s_qc[Hz];
    __shared__ float s_bq[Hz];
    __shared__ float s_hhold[Hz], s_c[Hz];
    __shared__ float s_dec[2];
    __shared__ float s_wm[4];
    __shared__ int   s_wi[4];
    __shared__ float s_ws[4];
    __shared__ int   s_imax;
    __shared__ int   s_dnz;

    // ---- phase 0: tables + weights + per-thread position data ----
    if (t < Hz) {
        float a0 = g_coef[t], a1 = g_coef[Hz + t];
        float dd = g_coef[2 * Hz + t], C = g_coef[3 * Hz + t];
        float wv = W_att[t];
        s_a0[t] = a0; s_a1[t] = a1; s_dd[t] = dd; s_Cg[t] = C; s_w[t] = wv;
        s_hhold[t] = 0.f; s_c[t] = 0.f; s_bq[t] = b_q[t];
    }
    for (int idx = t; idx < Hz * Hz; idx += NT) s_wq[idx] = W_q[idx];
    for (int idx = t; idx < 32 * Hz; idx += NT) {
        int ww = idx >> 7, col = idx & 127;
        int j = (ww >> 3) * Hz + k * 8 + (ww & 7);
        s_whh[idx] = W_hh[j * Hz + col];
    }
    if (t < 4 * Hz) {
        float2 u = g_U[t];
        s_uvv[t] = make_float4(u.x, u.y, g_V[t], 0.f);
    }
    if (t == 0) { s_imax = 0; s_dnz = 0; }
    __syncthreads();

    // position data (4 positions per thread; replicated across rg groups)
    const int s0 = k * SCHUNK + 4 * pg;
    const float4 x4 = *(const float4*)(st + (b * 2 + 0) * Sz + s0);
    const float4 y4 = *(const float4*)(st + (b * 2 + 1) * Sz + s0);
    const float4 d4 = *(const float4*)(dyn + b * Sz + s0);
    const ull XV0 = pack2(x4.x, x4.y), XV1 = pack2(x4.z, x4.w);
    const ull YV0 = pack2(y4.x, y4.y), YV1 = pack2(y4.z, y4.w);
    const ull DV0 = pack2(d4.x, d4.y), DV1 = pack2(d4.z, d4.w);

    // Mu = max |a0 x + a1 y + dd d| over this thread's positions x its 16 rows
    {
        float lmax = 0.f;
        #pragma unroll 4
        for (int i = 0; i < 16; ++i) {
            int g = rg * 16 + i;
            float a0 = s_a0[g], a1 = s_a1[g], dd = s_dd[g];
            float u0 = fmaf(a0, x4.x, fmaf(a1, y4.x, dd * d4.x));
            float u1 = fmaf(a0, x4.y, fmaf(a1, y4.y, dd * d4.y));
            float u2 = fmaf(a0, x4.z, fmaf(a1, y4.z, dd * d4.z));
            float u3 = fmaf(a0, x4.w, fmaf(a1, y4.w, dd * d4.w));
            lmax = fmaxf(lmax, fmaxf(fmaxf(fabsf(u0), fabsf(u1)),
                                     fmaxf(fabsf(u2), fabsf(u3))));
        }
        atomicMax(&s_imax, __float_as_int(lmax));
        if (rg == 0 && (d4.x != 0.f || d4.y != 0.f || d4.z != 0.f || d4.w != 0.f))
            s_dnz = 1;
    }
    __syncthreads();
    if (t == 0) {
        atomicMax(&g_bmax[b], s_imax);
        if (s_dnz) atomicMax(&g_dnz[b], 1);
    }
    batch_barrier(b);
    const float Mb = __int_as_float(__ldcg(&g_bmax[b]));
    const bool hasd = __ldcg(&g_dnz[b]) != 0;

    for (int step = 0; step <= STEPS; ++step) {
        // ---- head: warp 0 polls partner partials (tag >= step), combines, emits ----
        if (step > 0) {
            if (w == 0) {
                float m = -1e30f, ss = 0.f; int id = 0x7FFFFFFF;
                if (l < NBPB) {
                    const float4* slot = &g_part2[(step - 1) & 1][b][l];
                    unsigned tag;
                    do {
                        asm volatile("ld.acquire.gpu.global.u32 %0, [%1];"
                                     : "=r"(tag)
                                     : "l"((const unsigned*)&slot->w) : "memory");
                    } while ((int)tag < step);
                    float4 v = __ldcg(slot);
                    m = v.x; id = __float_as_int(v.y); ss = v.z;
                }
                #pragma unroll
                for (int off = 8; off > 0; off >>= 1) {
                    float mo = __shfl_down_sync(0xffffffffu, m, off);
                    int   io = __shfl_down_sync(0xffffffffu, id, off);
                    float so = __shfl_down_sync(0xffffffffu, ss, off);
                    SMAX_COMBINE(m, id, ss, mo, io, so);
                }
                if (l == 0) {
                    if (k == 0) {
                        float logp = -__logf(ss);
                        int oi = b * STEPS + (step - 1);
                        if (oi < out_size) out[oi] = (float)id;
                        int oj = Bz * STEPS + oi;
                        if (oj < out_size) out[oj] = logp;
                    }
                    s_dec[0] = st[(b * 2 + 0) * Sz + id];
                    s_dec[1] = st[(b * 2 + 1) * Sz + id];
                }
            }
        } else if (t == 0) { s_dec[0] = 0.f; s_dec[1] = 0.f; }
        __syncthreads();
        if (step == STEPS) break;

        // ---- LSTM finish + h update (redundant per block, bitwise identical) ----
        if (t < Hz) {
            float4 pgv = make_float4(0.f, 0.f, 0.f, 0.f);
            if (step > 0)
                pgv = __ldcg(&g_pg4[(step - 1) & 1][b][t]);
            float d0 = s_dec[0], d1 = s_dec[1];
            float4 u0 = s_uvv[t],          u1 = s_uvv[Hz + t],
                   u2 = s_uvv[2 * Hz + t], u3 = s_uvv[3 * Hz + t];
            float gi = pgv.x + fmaf(u0.x, d0, fmaf(u0.y, d1, u0.z));
            float gf = pgv.y + fmaf(u1.x, d0, fmaf(u1.y, d1, u1.z));
            float gc = pgv.z + fmaf(u2.x, d0, fmaf(u2.y, d1, u2.z));
            float go = pgv.w + fmaf(u3.x, d0, fmaf(u3.y, d1, u3.z));
            float c2 = fmaf(sigmoidf(gf), s_c[t], sigmoidf(gi) * tanhf(gc));
            float h2 = sigmoidf(go) * tanhf(c2);
            s_c[t] = c2;
            s_hhold[t] = h2;
        }
        __syncthreads();

        // ---- overlapped: warps 0-15 q-matvec (8 rows each) + tab4/qc/max;
        //      warps 16-31 gate partials (2 rows each) -> g_pg4 ----
        if (w < 16) {
            int row = w * 8;
            float h0 = s_hhold[l], h1 = s_hhold[l + 32],
                  h2 = s_hhold[l + 64], h3 = s_hhold[l + 96];
            float a[8];
            #pragma unroll
            for (int r8 = 0; r8 < 8; ++r8) {
                const float* wq = s_wq + (row + r8) * Hz;
                a[r8] = fmaf(wq[l], h0, fmaf(wq[l + 32], h1,
                        fmaf(wq[l + 64], h2, wq[l + 96] * h3)));
            }
            #pragma unroll
            for (int off = 16; off > 0; off >>= 1) {
                #pragma unroll
                for (int r8 = 0; r8 < 8; ++r8)
                    a[r8] += __shfl_down_sync(0xffffffffu, a[r8], off);
            }
            if (l == 0) {
                float lmax = 0.f;
                #pragma unroll
                for (int r8 = 0; r8 < 8; ++r8) {
                    int r = row + r8;
                    float qc = (a[r8] + s_bq[r]) + s_Cg[r];
                    s_qc[r] = qc;
                    s_tab4[r] = make_float4(s_a0[r], s_a1[r], qc, s_w[r]);
                    lmax = fmaxf(lmax, fabsf(qc));
                }
                s_wm32[w] = lmax;
            }
        } else {
            int ww = w - 16;
            #pragma unroll
            for (int rr = 0; rr < 2; ++rr) {
                int row = ww * 2 + rr;
                const float* whr = s_whh + row * Hz;
                float acc = fmaf(whr[l],      s_hhold[l],
                            fmaf(whr[l + 32], s_hhold[l + 32],
                            fmaf(whr[l + 64], s_hhold[l + 64],
                                 whr[l + 96] * s_hhold[l + 96])));
                #pragma unroll
                for (int off = 16; off > 0; off >>= 1)
                    acc += __shfl_down_sync(0xffffffffu, acc, off);
                if (l == 0) {
                    int q4 = row >> 3, r = k * 8 + (row & 7);
                    float* dst = (float*)&g_pg4[step & 1][b][r];
                    asm volatile("st.global.f32 [%0], %1;"
                                 :: "l"(dst + q4), "f"(acc) : "memory");
                }
            }
        }
        __syncthreads();

        // ---- bound + path (per-thread, from 16 warp maxima) ----
        float bound;
        {
            const float4* wmp = (const float4*)s_wm32;
            float4 m0 = wmp[0], m1 = wmp[1], m2 = wmp[2], m3 = wmp[3];
            float4 mm4;
            mm4.x = fmaxf(fmaxf(m0.x, m1.x), fmaxf(m2.x, m3.x));
            mm4.y = fmaxf(fmaxf(m0.y, m1.y), fmaxf(m2.y, m3.y));
            mm4.z = fmaxf(fmaxf(m0.z, m1.z), fmaxf(m2.z, m3.z));
            mm4.w = fmaxf(fmaxf(m0.w, m1.w), fmaxf(m2.w, m3.w));
            bound = fmaxf(fmaxf(mm4.x, mm4.y), fmaxf(mm4.z, mm4.w)) + Mb;
        }
        const int path = (bound <= 0.23f) ? 0
                       : (bound <= 0.32f) ? 1
                       : (bound <= 0.55f) ? 2 : 3;

        // ---- attention scan: on-the-fly base, 4 positions x 16 rows/thread ----
        ull A0 = 0ull, A1 = 0ull;
        if (path <= 2) {
            if (!hasd) {
                if (path == 0)
                    scan16b<3, false>(rg * 16, XV0, XV1, YV0, YV1, DV0, DV1, s_tab4, s_dd, A0, A1);
                else if (path == 1)
                    scan16b<4, false>(rg * 16, XV0, XV1, YV0, YV1, DV0, DV1, s_tab4, s_dd, A0, A1);
                else
                    scan16b<6, false>(rg * 16, XV0, XV1, YV0, YV1, DV0, DV1, s_tab4, s_dd, A0, A1);
            } else {
                if (path == 0)
                    scan16b<3, true>(rg * 16, XV0, XV1, YV0, YV1, DV0, DV1, s_tab4, s_dd, A0, A1);
                else if (path == 1)
                    scan16b<4, true>(rg * 16, XV0, XV1, YV0, YV1, DV0, DV1, s_tab4, s_dd, A0, A1);
                else
                    scan16b<6, true>(rg * 16, XV0, XV1, YV0, YV1, DV0, DV1, s_tab4, s_dd, A0, A1);
            }
        } else {
            float f0 = 0.f, f1 = 0.f, f2 = 0.f, f3 = 0.f;
            for (int i = 0; i < 16; ++i) {
                int g = rg * 16 + i;
                float a0 = s_a0[g], a1 = s_a1[g], dd = s_dd[g];
                float qc = s_qc[g], wv = s_w[g];
                f0 = fmaf(wv, tanhf(fmaf(a0, x4.x, fmaf(a1, y4.x, fmaf(dd, d4.x, qc)))), f0);
                f1 = fmaf(wv, tanhf(fmaf(a0, x4.y, fmaf(a1, y4.y, fmaf(dd, d4.y, qc)))), f1);
                f2 = fmaf(wv, tanhf(fmaf(a0, x4.z, fmaf(a1, y4.z, fmaf(dd, d4.z, qc)))), f2);
                f3 = fmaf(wv, tanhf(fmaf(a0, x4.w, fmaf(a1, y4.w, fmaf(dd, d4.w, qc)))), f3);
            }
            A0 = pack2(f0, f1); A1 = pack2(f2, f3);
        }
        {
            ulonglong2 vv; vv.x = A0; vv.y = A1;
            s_acc[rg * 128 + pg] = vv;
        }
        __syncthreads();

        // ---- reduce 8 row-groups -> block softmax partial ----
        if (t < 128) {
            ull B0 = 0ull, B1 = 0ull;
            #pragma unroll
            for (int r = 0; r < 8; ++r) {
                ulonglong2 v = s_acc[r * 128 + t];
                B0 = f2add(B0, v.x); B1 = f2add(B1, v.y);
            }
            float a0, a1, a2, a3;
            unpack2(B0, a0, a1); unpack2(B1, a2, a3);
            // replicate reference fp32 quantization `attns + 10000.0`
            float aq0 = a0 + 10000.0f, aq1 = a1 + 10000.0f;
            float aq2 = a2 + 10000.0f, aq3 = a3 + 10000.0f;
            int sb = k * SCHUNK + 4 * t;
            float m, ss; int id;
            if (aq1 > aq0) { m = aq1; id = sb + 1; ss = __expf(aq0 - aq1) + 1.f; }
            else           { m = aq0; id = sb;     ss = 1.f + __expf(aq1 - aq0); }
            float m2, ss2; int id2;
            if (aq3 > aq2) { m2 = aq3; id2 = sb + 3; ss2 = __expf(aq2 - aq3) + 1.f; }
            else           { m2 = aq2; id2 = sb + 2; ss2 = 1.f + __expf(aq3 - aq2); }
            SMAX_COMBINE(m, id, ss, m2, id2, ss2);
            #pragma unroll
            for (int off = 16; off > 0; off >>= 1) {
                float mo = __shfl_down_sync(0xffffffffu, m, off);
                int   io = __shfl_down_sync(0xffffffffu, id, off);
                float so = __shfl_down_sync(0xffffffffu, ss, off);
                SMAX_COMBINE(m, id, ss, mo, io, so);
            }
            if (l == 0) { s_wm[w] = m; s_wi[w] = id; s_ws[w] = ss; }
        }
        __syncthreads();
        if (t < 32) {
            float m  = (t < 4) ? s_wm[t] : -1e30f;
            int   id = (t < 4) ? s_wi[t] : 0x7FFFFFFF;
            float ss = (t < 4) ? s_ws[t] : 0.f;
            #pragma unroll
            for (int off = 2; off > 0; off >>= 1) {
                float mo = __shfl_down_sync(0xffffffffu, m, off);
                int   io = __shfl_down_sync(0xffffffffu, id, off);
                float so = __shfl_down_sync(0xffffffffu, ss, off);
                SMAX_COMBINE(m, id, ss, mo, io, so);
            }
            if (t == 0) {
                // publish payload, then release the tag (covers g_pg4 stores too:
                // they happen-before via __syncthreads + this gpu-scope fence)
                float4* slot = &g_part2[step & 1][b][k];
                asm volatile("fence.acq_rel.gpu;" ::: "memory");
                asm volatile("st.global.v2.f32 [%0], {%1, %2};"
                             :: "l"(&slot->x), "f"(m), "f"(__int_as_float(id)) : "memory");
                asm volatile("st.global.f32 [%0], %1;"
                             :: "l"(&slot->z), "f"(ss) : "memory");
                asm volatile("st.release.gpu.global.u32 [%0], %1;"
                             :: "l"((unsigned*)&slot->w), "r"((unsigned)(step + 1)) : "memory");
            }
        }
        // no barrier: next head polls the tags directly
    }

    // ---- teardown: reset tags for next graph replay ----
    batch_barrier(b);
    if (t == 0) {
        *(unsigned*)&g_part2[0][b][k].w = 0u;
        *(unsigned*)&g_part2[1][b][k].w = 0u;
    }
}

extern "C" void kernel_launch(void* const* d_in, const int* in_sizes, int n_in,
                              void* d_out, int out_size) {
    const float* st    = (const float*)d_in[0];
    const float* dyn   = (const float*)d_in[1];
    const float* W_s   = (const float*)d_in[2];
    const float* b_s   = (const float*)d_in[3];
    const float* W_d   = (const float*)d_in[4];
    const float* b_d   = (const float*)d_in[5];
    const float* W_dec = (const float*)d_in[6];
    const float* b_dec = (const float*)d_in[7];
    const float* W_ih  = (const float*)d_in[8];
    const float* W_hh  = (const float*)d_in[9];
    const float* b_ih  = (const float*)d_in[10];
    const float* b_hh  = (const float*)d_in[11];
    const float* W_ref = (const float*)d_in[12];
    const float* b_ref = (const float*)d_in[13];
    const float* W_pd  = (const float*)d_in[14];
    const float* b_pd  = (const float*)d_in[15];
    const float* W_q   = (const float*)d_in[16];
    const float* b_q   = (const float*)d_in[17];
    const float* W_att = (const float*)d_in[18];

    const int dyn_smem = (Hz * Hz) * (int)sizeof(float) + 8 * 128 * 16;  // 64K + 16K
    static int attr_set = 0;
    if (!attr_set) {
        cudaFuncSetAttribute(persist_kernel,
                             cudaFuncAttributeMaxDynamicSharedMemorySize, dyn_smem);
        attr_set = 1;
    }

    coef_kernel<<<640, 128>>>(W_ref, W_s, b_s, b_ref, W_pd, W_d, b_d, b_pd,
                              W_ih, W_dec, b_dec, b_ih, b_hh);
    persist_kernel<<<NB, NT, dyn_smem>>>(st, dyn, W_hh, W_q, b_q, W_att,
                                         (float*)d_out, out_size);
}

// round 17
// speedup vs baseline: 1.0567x; 1.0567x over previous
#include <cuda_runtime.h>
#include <math.h>

#define Bz 8
#define Sz 8192
#define Hz 128
#define STEPS 20
#define NBPB 16              // blocks per batch
#define NB (Bz * NBPB)       // 128 blocks (<=148 SMs -> co-resident)
#define NT 1024              // 32 warps/block
#define SCHUNK 512           // positions per block

typedef unsigned long long ull;

// -------- persistent scratch --------
__device__ float  g_coef[4 * Hz];   // a0 | a1 | dd | C
__device__ float2 g_U[4 * Hz];      // W_ih @ W_dec
__device__ float  g_V[4 * Hz];      // W_ih @ b_dec + b_ih + b_hh
__device__ __align__(16) float4 g_pg4[2][Bz][Hz];     // gate partials {i,f,c,o}, dbl-buffered
__device__ __align__(16) float4 g_part2[2][Bz][NBPB]; // {m, id-bits, ssum, tag-bits}
__device__ int      g_bmax[Bz];
__device__ int      g_dnz[Bz];
__device__ unsigned g_bcnt[Bz];
__device__ unsigned g_bgen[Bz];

// -------- batch-local barrier (used only at init and teardown) --------
__device__ __forceinline__ void batch_barrier(int b) {
    __syncthreads();
    if (threadIdx.x == 0) {
        unsigned gen;
        asm volatile("ld.acquire.gpu.global.u32 %0, [%1];"
                     : "=r"(gen) : "l"(&g_bgen[b]) : "memory");
        unsigned arrived;
        asm volatile("atom.acq_rel.gpu.global.add.u32 %0, [%1], %2;"
                     : "=r"(arrived) : "l"(&g_bcnt[b]), "r"(1u) : "memory");
        if (arrived == NBPB - 1) {
            asm volatile("st.global.u32 [%0], %1;" :: "l"(&g_bcnt[b]), "r"(0u) : "memory");
            asm volatile("st.release.gpu.global.u32 [%0], %1;"
                         :: "l"(&g_bgen[b]), "r"(gen + 1u) : "memory");
        } else {
            unsigned cur;
            do {
                asm volatile("ld.acquire.gpu.global.u32 %0, [%1];"
                             : "=r"(cur) : "l"(&g_bgen[b]) : "memory");
            } while (cur == gen);
        }
    }
    __syncthreads();
}

// -------- packed f32x2 helpers --------
__device__ __forceinline__ ull f2add(ull a, ull b) {
    ull d; asm("add.rn.f32x2 %0, %1, %2;" : "=l"(d) : "l"(a), "l"(b)); return d;
}
__device__ __forceinline__ ull f2mul(ull a, ull b) {
    ull d; asm("mul.rn.f32x2 %0, %1, %2;" : "=l"(d) : "l"(a), "l"(b)); return d;
}
__device__ __forceinline__ ull f2fma(ull a, ull b, ull c) {
    ull d; asm("fma.rn.f32x2 %0, %1, %2, %3;" : "=l"(d) : "l"(a), "l"(b), "l"(c)); return d;
}
__device__ __forceinline__ ull dup2(float f) {
    ull d; asm("mov.b64 %0, {%1, %2};" : "=l"(d) : "f"(f), "f"(f)); return d;
}
__device__ __forceinline__ ull pack2(float lo, float hi) {
    ull d; asm("mov.b64 %0, {%1, %2};" : "=l"(d) : "f"(lo), "f"(hi)); return d;
}
__device__ __forceinline__ void unpack2(ull v, float& lo, float& hi) {
    asm("mov.b64 {%0, %1}, %2;" : "=f"(lo), "=f"(hi) : "l"(v));
}

// tanh Taylor tail: NC=3 deg-7 (|x|<=0.23), NC=4 deg-9 (|x|<=0.32), NC=6 deg-13 (|x|<=0.55)
template<int NC>
__device__ __forceinline__ ull poly_core(ull X, ull wd, ull A) {
    const ull C1 = dup2(-0.33333334f);
    const ull C2 = dup2( 0.13333334f);
    const ull C3 = dup2(-0.053968254f);
    const ull C4 = dup2( 0.021869489f);
    const ull C5 = dup2(-0.008863236f);
    const ull C6 = dup2( 0.0035921280f);
    const ull ONE = dup2(1.0f);
    ull Y = f2mul(X, X);
    ull P;
    if (NC == 6) {
        P = f2fma(Y, C6, C5);
        P = f2fma(P, Y, C4);
        P = f2fma(P, Y, C3);
        P = f2fma(P, Y, C2);
    } else if (NC == 4) {
        P = f2fma(Y, C4, C3);
        P = f2fma(P, Y, C2);
    } else {
        P = f2fma(Y, C3, C2);
    }
    P = f2fma(P, Y, C1);
    P = f2fma(P, Y, ONE);
    return f2fma(wd, f2mul(X, P), A);
}

// 16 rows x 4 positions per thread; one LDS.128 per row; ALU dup expansion
template<int NC, bool HASD>
__device__ __forceinline__ void scan16b(int g0,
                                        ull XV0, ull XV1, ull YV0, ull YV1,
                                        ull DV0, ull DV1,
                                        const float4* __restrict__ s_tab4,
                                        const float* __restrict__ s_ddt,
                                        ull& A0, ull& A1) {
    #pragma unroll
    for (int i = 0; i < 16; ++i) {
        int g = g0 + i;
        float4 v = s_tab4[g];                 // {a0, a1, q+C, w}
        ull a0d = dup2(v.x), a1d = dup2(v.y);
        ull qd  = dup2(v.z), wd  = dup2(v.w);
        ull X0 = f2fma(a1d, YV0, qd);
        ull X1 = f2fma(a1d, YV1, qd);
        X0 = f2fma(a0d, XV0, X0);
        X1 = f2fma(a0d, XV1, X1);
        if (HASD) {
            ull ddd = dup2(s_ddt[g]);
            X0 = f2fma(ddd, DV0, X0);
            X1 = f2fma(ddd, DV1, X1);
        }
        A0 = poly_core<NC>(X0, wd, A0);
        A1 = poly_core<NC>(X1, wd, A1);
    }
}

__device__ __forceinline__ float sigmoidf(float x) { return 1.f / (1.f + expf(-x)); }

#define SMAX_COMBINE(m, id, ss, mo, io, so)                          \
    if ((mo) > (m) || ((mo) == (m) && (io) < (id))) {                \
        (ss) = (ss) * __expf((m) - (mo)) + (so);                     \
        (m) = (mo); (id) = (io);                                     \
    } else {                                                         \
        (ss) = (ss) + (so) * __expf((mo) - (m));                     \
    }

// -------- K0: coalesced fold. 640 blocks x 128 thr: one output row each --------
__global__ void coef_kernel(const float* __restrict__ W_ref, const float* __restrict__ W_s,
                            const float* __restrict__ b_s,   const float* __restrict__ b_ref,
                            const float* __restrict__ W_pd,  const float* __restrict__ W_d,
                            const float* __restrict__ b_d,   const float* __restrict__ b_pd,
                            const float* __restrict__ W_ih,  const float* __restrict__ W_dec,
                            const float* __restrict__ b_dec, const float* __restrict__ b_ih,
                            const float* __restrict__ b_hh) {
    __shared__ float s_r[4][4];
    const int h = threadIdx.x, w = h >> 5, l = h & 31;
    float v0, v1, v2, v3;
    if (blockIdx.x < 512) {
        int j = blockIdx.x;
        float wij = W_ih[j * Hz + h];
        v0 = wij * W_dec[h * 2 + 0];
        v1 = wij * W_dec[h * 2 + 1];
        v2 = wij * b_dec[h];
        v3 = 0.f;
    } else {
        int g = blockIdx.x - 512;
        float wr = W_ref[g * Hz + h];
        float wp = W_pd[g * Hz + h];
        v0 = wr * W_s[h * 2 + 0];
        v1 = wr * W_s[h * 2 + 1];
        v2 = fmaf(wr, b_s[h], wp * b_d[h]);
        v3 = wp * W_d[h];
    }
    #pragma unroll
    for (int off = 16; off > 0; off >>= 1) {
        v0 += __shfl_down_sync(0xffffffffu, v0, off);
        v1 += __shfl_down_sync(0xffffffffu, v1, off);
        v2 += __shfl_down_sync(0xffffffffu, v2, off);
        v3 += __shfl_down_sync(0xffffffffu, v3, off);
    }
    if (l == 0) { s_r[0][w] = v0; s_r[1][w] = v1; s_r[2][w] = v2; s_r[3][w] = v3; }
    __syncthreads();
    if (h == 0) {
        float r0 = s_r[0][0] + s_r[0][1] + s_r[0][2] + s_r[0][3];
        float r1 = s_r[1][0] + s_r[1][1] + s_r[1][2] + s_r[1][3];
        float r2 = s_r[2][0] + s_r[2][1] + s_r[2][2] + s_r[2][3];
        float r3 = s_r[3][0] + s_r[3][1] + s_r[3][2] + s_r[3][3];
        if (blockIdx.x < 512) {
            int j = blockIdx.x;
            g_U[j] = make_float2(r0, r1);
            g_V[j] = r2 + b_ih[j] + b_hh[j];
        } else {
            int g = blockIdx.x - 512;
            g_coef[g] = r0;                               // a0
            g_coef[Hz + g] = r1;                          // a1
            g_coef[2 * Hz + g] = r3;                      // dd
            g_coef[3 * Hz + g] = r2 + b_ref[g] + b_pd[g]; // C
        }
    }
}

// -------- persistent decode kernel --------
__global__ __launch_bounds__(NT, 1)
void persist_kernel(const float* __restrict__ st,  const float* __restrict__ dyn,
                    const float* __restrict__ W_hh, const float* __restrict__ W_q,
                    const float* __restrict__ b_q,  const float* __restrict__ W_att,
                    float* __restrict__ out, int out_size) {
    const int blk = blockIdx.x;
    const int b = blk / NBPB;
    const int k = blk % NBPB;
    const int t = threadIdx.x;
    const int w = t >> 5, l = t & 31;
    const int pg = t & 127, rg = t >> 7;

    extern __shared__ float dsm[];
    float* s_wq = dsm;                                   // 64 KB
    ulonglong2* s_acc = (ulonglong2*)(dsm + Hz * Hz);    // 16 KB

    __shared__ float s_whh[32 * Hz];                     // 16 KB
    __shared__ __align__(16) float4 s_uvv[4 * Hz];       // 8 KB
    __shared__ __align__(16) float4 s_tab4[Hz];          // {a0, a1, q+C, w} per step
    __shared__ float s_a0[Hz], s_a1[Hz], s_dd[Hz], s_w[Hz], s_Cg[Hz], s_qc[Hz];
    __shared__ float s_qraw[Hz], s_bq[Hz];
    __shared__ float s_hhold[Hz], s_c[Hz];
    __shared__ float s_dec[2];
    __shared__ float s_wm[4];
    __shared__ int   s_wi[4];
    __shared__ float s_ws[4];
    __shared__ int   s_imax;
    __shared__ int   s_dnz;

    // ---- phase 0: tables + weights + per-thread position data ----
    if (t < Hz) {
        float a0 = g_coef[t], a1 = g_coef[Hz + t];
        float dd = g_coef[2 * Hz + t], C = g_coef[3 * Hz + t];
        float wv = W_att[t];
        s_a0[t] = a0; s_a1[t] = a1; s_dd[t] = dd; s_Cg[t] = C; s_w[t] = wv;
        s_hhold[t] = 0.f; s_c[t] = 0.f; s_bq[t] = b_q[t];
    }
    for (int idx = t; idx < Hz * Hz; idx += NT) s_wq[idx] = W_q[idx];
    for (int idx = t; idx < 32 * Hz; idx += NT) {
        int ww = idx >> 7, col = idx & 127;
        int j = (ww >> 3) * Hz + k * 8 + (ww & 7);
        s_whh[idx] = W_hh[j * Hz + col];
    }
    if (t < 4 * Hz) {
        float2 u = g_U[t];
        s_uvv[t] = make_float4(u.x, u.y, g_V[t], 0.f);
    }
    if (t == 0) { s_imax = 0; s_dnz = 0; }
    __syncthreads();

    // position data (4 positions per thread; replicated across rg groups)
    const int s0 = k * SCHUNK + 4 * pg;
    const float4 x4 = *(const float4*)(st + (b * 2 + 0) * Sz + s0);
    const float4 y4 = *(const float4*)(st + (b * 2 + 1) * Sz + s0);
    const float4 d4 = *(const float4*)(dyn + b * Sz + s0);
    const ull XV0 = pack2(x4.x, x4.y), XV1 = pack2(x4.z, x4.w);
    const ull YV0 = pack2(y4.x, y4.y), YV1 = pack2(y4.z, y4.w);
    const ull DV0 = pack2(d4.x, d4.y), DV1 = pack2(d4.z, d4.w);

    // Mu = max |a0 x + a1 y + dd d| over this thread's positions x its 16 rows
    {
        float lmax = 0.f;
        #pragma unroll 4
        for (int i = 0; i < 16; ++i) {
            int g = rg * 16 + i;
            float a0 = s_a0[g], a1 = s_a1[g], dd = s_dd[g];
            float u0 = fmaf(a0, x4.x, fmaf(a1, y4.x, dd * d4.x));
            float u1 = fmaf(a0, x4.y, fmaf(a1, y4.y, dd * d4.y));
            float u2 = fmaf(a0, x4.z, fmaf(a1, y4.z, dd * d4.z));
            float u3 = fmaf(a0, x4.w, fmaf(a1, y4.w, dd * d4.w));
            lmax = fmaxf(lmax, fmaxf(fmaxf(fabsf(u0), fabsf(u1)),
                                     fmaxf(fabsf(u2), fabsf(u3))));
        }
        atomicMax(&s_imax, __float_as_int(lmax));
        if (rg == 0) {
            int nz = (d4.x != 0.f || d4.y != 0.f || d4.z != 0.f || d4.w != 0.f) ? 1 : 0;
            if (nz) s_dnz = 1;
        }
    }
    __syncthreads();
    if (t == 0) {
        atomicMax(&g_bmax[b], s_imax);
        if (s_dnz) atomicMax(&g_dnz[b], 1);
    }
    batch_barrier(b);
    const float Mb = __int_as_float(__ldcg(&g_bmax[b]));
    const bool hasd = __ldcg(&g_dnz[b]) != 0;

    for (int step = 0; step <= STEPS; ++step) {
        // ---- head: poll partner partials (tag >= step), combine, emit, gather ----
        if (step > 0) {
            if (w == 0) {
                float m = -1e30f, ss = 0.f; int id = 0x7FFFFFFF;
                if (l < NBPB) {
                    const float4* slot = &g_part2[(step - 1) & 1][b][l];
                    unsigned tag;
                    do {
                        asm volatile("ld.acquire.gpu.global.u32 %0, [%1];"
                                     : "=r"(tag)
                                     : "l"((const unsigned*)&slot->w) : "memory");
                    } while ((int)tag < step);
                    float4 v = __ldcg(slot);
                    m = v.x; id = __float_as_int(v.y); ss = v.z;
                }
                #pragma unroll
                for (int off = 8; off > 0; off >>= 1) {
                    float mo = __shfl_down_sync(0xffffffffu, m, off);
                    int   io = __shfl_down_sync(0xffffffffu, id, off);
                    float so = __shfl_down_sync(0xffffffffu, ss, off);
                    SMAX_COMBINE(m, id, ss, mo, io, so);
                }
                if (l == 0) {
                    if (k == 0) {
                        float logp = -__logf(ss);
                        int oi = b * STEPS + (step - 1);
                        if (oi < out_size) out[oi] = (float)id;
                        int oj = Bz * STEPS + oi;
                        if (oj < out_size) out[oj] = logp;
                    }
                    s_dec[0] = st[(b * 2 + 0) * Sz + id];
                    s_dec[1] = st[(b * 2 + 1) * Sz + id];
                }
            }
        } else if (t == 0) { s_dec[0] = 0.f; s_dec[1] = 0.f; }
        __syncthreads();
        if (step == STEPS) break;

        // ---- LSTM finish + h update (redundant per block, bitwise identical) ----
        if (t < Hz) {
            float4 pgv = make_float4(0.f, 0.f, 0.f, 0.f);
            if (step > 0)
                pgv = __ldcg(&g_pg4[(step - 1) & 1][b][t]);
            float d0 = s_dec[0], d1 = s_dec[1];
            float4 u0 = s_uvv[t],          u1 = s_uvv[Hz + t],
                   u2 = s_uvv[2 * Hz + t], u3 = s_uvv[3 * Hz + t];
            float gi = pgv.x + fmaf(u0.x, d0, fmaf(u0.y, d1, u0.z));
            float gf = pgv.y + fmaf(u1.x, d0, fmaf(u1.y, d1, u1.z));
            float gc = pgv.z + fmaf(u2.x, d0, fmaf(u2.y, d1, u2.z));
            float go = pgv.w + fmaf(u3.x, d0, fmaf(u3.y, d1, u3.z));
            float c2 = fmaf(sigmoidf(gf), s_c[t], sigmoidf(gi) * tanhf(gc));
            float h2 = sigmoidf(go) * tanhf(c2);
            s_c[t] = c2;
            s_hhold[t] = h2;
        }
        __syncthreads();

        // ---- q = W_q @ h + b_q (all from smem; redundant per block) ----
        {
            #pragma unroll
            for (int r4 = 0; r4 < 4; ++r4) {
                int row = w * 4 + r4;
                const float* wq = s_wq + row * Hz;
                float acc = fmaf(wq[l],      s_hhold[l],
                            fmaf(wq[l + 32], s_hhold[l + 32],
                            fmaf(wq[l + 64], s_hhold[l + 64],
                                 wq[l + 96] * s_hhold[l + 96])));
                #pragma unroll
                for (int off = 16; off > 0; off >>= 1)
                    acc += __shfl_down_sync(0xffffffffu, acc, off);
                if (l == 0) s_qraw[row] = acc + s_bq[row];
            }
        }
        __syncthreads();
        if (t < Hz) {
            float qc = s_qraw[t] + s_Cg[t];
            s_qc[t] = qc;
            s_tab4[t] = make_float4(s_a0[t], s_a1[t], qc, s_w[t]);
            float mq = fabsf(qc);
            #pragma unroll
            for (int off = 16; off > 0; off >>= 1)
                mq = fmaxf(mq, __shfl_down_sync(0xffffffffu, mq, off));
            if (l == 0) s_wm[w] = mq;
        }
        __syncthreads();
        const float bound = fmaxf(fmaxf(s_wm[0], s_wm[1]), fmaxf(s_wm[2], s_wm[3])) + Mb;
        const int path = (bound <= 0.23f) ? 0
                       : (bound <= 0.32f) ? 1
                       : (bound <= 0.55f) ? 2 : 3;

        // ---- attention scan: on-the-fly base, 4 positions x 16 rows/thread ----
        ull A0 = 0ull, A1 = 0ull;
        if (path <= 2) {
            if (!hasd) {
                if (path == 0)
                    scan16b<3, false>(rg * 16, XV0, XV1, YV0, YV1, DV0, DV1, s_tab4, s_dd, A0, A1);
                else if (path == 1)
                    scan16b<4, false>(rg * 16, XV0, XV1, YV0, YV1, DV0, DV1, s_tab4, s_dd, A0, A1);
                else
                    scan16b<6, false>(rg * 16, XV0, XV1, YV0, YV1, DV0, DV1, s_tab4, s_dd, A0, A1);
            } else {
                if (path == 0)
                    scan16b<3, true>(rg * 16, XV0, XV1, YV0, YV1, DV0, DV1, s_tab4, s_dd, A0, A1);
                else if (path == 1)
                    scan16b<4, true>(rg * 16, XV0, XV1, YV0, YV1, DV0, DV1, s_tab4, s_dd, A0, A1);
                else
                    scan16b<6, true>(rg * 16, XV0, XV1, YV0, YV1, DV0, DV1, s_tab4, s_dd, A0, A1);
            }
        } else {
            float f0 = 0.f, f1 = 0.f, f2 = 0.f, f3 = 0.f;
            for (int i = 0; i < 16; ++i) {
                int g = rg * 16 + i;
                float a0 = s_a0[g], a1 = s_a1[g], dd = s_dd[g];
                float qc = s_qc[g], wv = s_w[g];
                f0 = fmaf(wv, tanhf(fmaf(a0, x4.x, fmaf(a1, y4.x, fmaf(dd, d4.x, qc)))), f0);
                f1 = fmaf(wv, tanhf(fmaf(a0, x4.y, fmaf(a1, y4.y, fmaf(dd, d4.y, qc)))), f1);
                f2 = fmaf(wv, tanhf(fmaf(a0, x4.z, fmaf(a1, y4.z, fmaf(dd, d4.z, qc)))), f2);
                f3 = fmaf(wv, tanhf(fmaf(a0, x4.w, fmaf(a1, y4.w, fmaf(dd, d4.w, qc)))), f3);
            }
            A0 = pack2(f0, f1); A1 = pack2(f2, f3);
        }
        {
            ulonglong2 vv; vv.x = A0; vv.y = A1;
            s_acc[rg * 128 + pg] = vv;
        }

        // ---- gate partials for NEXT step (all warps; before the sync) ----
        {
            const float* whr = s_whh + w * Hz;
            float acc = fmaf(whr[l],      s_hhold[l],
                        fmaf(whr[l + 32], s_hhold[l + 32],
                        fmaf(whr[l + 64], s_hhold[l + 64],
                             whr[l + 96] * s_hhold[l + 96])));
            #pragma unroll
            for (int off = 16; off > 0; off >>= 1)
                acc += __shfl_down_sync(0xffffffffu, acc, off);
            if (l == 0) {
                int q4 = w >> 3, r = k * 8 + (w & 7);
                float* dst = (float*)&g_pg4[step & 1][b][r];
                asm volatile("st.global.f32 [%0], %1;"
                             :: "l"(dst + q4), "f"(acc) : "memory");
            }
        }
        __syncthreads();

        // ---- reduce 8 row-groups -> block softmax partial ----
        if (t < 128) {
            ull B0 = 0ull, B1 = 0ull;
            #pragma unroll
            for (int r = 0; r < 8; ++r) {
                ulonglong2 v = s_acc[r * 128 + t];
                B0 = f2add(B0, v.x); B1 = f2add(B1, v.y);
            }
            float a0, a1, a2, a3;
            unpack2(B0, a0, a1); unpack2(B1, a2, a3);
            // replicate reference fp32 quantization `attns + 10000.0`
            float aq0 = a0 + 10000.0f, aq1 = a1 + 10000.0f;
            float aq2 = a2 + 10000.0f, aq3 = a3 + 10000.0f;
            int sb = k * SCHUNK + 4 * t;
            float m, ss; int id;
            if (aq1 > aq0) { m = aq1; id = sb + 1; ss = __expf(aq0 - aq1) + 1.f; }
            else           { m = aq0; id = sb;     ss = 1.f + __expf(aq1 - aq0); }
            float m2, ss2; int id2;
            if (aq3 > aq2) { m2 = aq3; id2 = sb + 3; ss2 = __expf(aq2 - aq3) + 1.f; }
            else           { m2 = aq2; id2 = sb + 2; ss2 = 1.f + __expf(aq3 - aq2); }
            SMAX_COMBINE(m, id, ss, m2, id2, ss2);
            #pragma unroll
            for (int off = 16; off > 0; off >>= 1) {
                float mo = __shfl_down_sync(0xffffffffu, m, off);
                int   io = __shfl_down_sync(0xffffffffu, id, off);
                float so = __shfl_down_sync(0xffffffffu, ss, off);
                SMAX_COMBINE(m, id, ss, mo, io, so);
            }
            if (l == 0) { s_wm[w] = m; s_wi[w] = id; s_ws[w] = ss; }
        }
        __syncthreads();
        if (t < 32) {
            float m  = (t < 4) ? s_wm[t] : -1e30f;
            int   id = (t < 4) ? s_wi[t] : 0x7FFFFFFF;
            float ss = (t < 4) ? s_ws[t] : 0.f;
            #pragma unroll
            for (int off = 2; off > 0; off >>= 1) {
                float mo = __shfl_down_sync(0xffffffffu, m, off);
                int   io = __shfl_down_sync(0xffffffffu, id, off);
                float so = __shfl_down_sync(0xffffffffu, ss, off);
                SMAX_COMBINE(m, id, ss, mo, io, so);
            }
            if (t == 0) {
                // publish payload, then release the tag (covers g_pg4 stores too:
                // they happen-before via __syncthreads + this gpu-scope fence)
                float4* slot = &g_part2[step & 1][b][k];
                asm volatile("fence.acq_rel.gpu;" ::: "memory");
                asm volatile("st.global.v2.f32 [%0], {%1, %2};"
                             :: "l"(&slot->x), "f"(m), "f"(__int_as_float(id)) : "memory");
                asm volatile("st.global.f32 [%0], %1;"
                             :: "l"(&slot->z), "f"(ss) : "memory");
                asm volatile("st.release.gpu.global.u32 [%0], %1;"
                             :: "l"((unsigned*)&slot->w), "r"((unsigned)(step + 1)) : "memory");
            }
        }
        // no barrier: next head polls the tags directly
    }

    // ---- teardown: all blocks done reading; reset tags for the next replay ----
    batch_barrier(b);
    if (t == 0) {
        *(unsigned*)&g_part2[0][b][k].w = 0u;
        *(unsigned*)&g_part2[1][b][k].w = 0u;
    }
}

extern "C" void kernel_launch(void* const* d_in, const int* in_sizes, int n_in,
                              void* d_out, int out_size) {
    const float* st    = (const float*)d_in[0];
    const float* dyn   = (const float*)d_in[1];
    const float* W_s   = (const float*)d_in[2];
    const float* b_s   = (const float*)d_in[3];
    const float* W_d   = (const float*)d_in[4];
    const float* b_d   = (const float*)d_in[5];
    const float* W_dec = (const float*)d_in[6];
    const float* b_dec = (const float*)d_in[7];
    const float* W_ih  = (const float*)d_in[8];
    const float* W_hh  = (const float*)d_in[9];
    const float* b_ih  = (const float*)d_in[10];
    const float* b_hh  = (const float*)d_in[11];
    const float* W_ref = (const float*)d_in[12];
    const float* b_ref = (const float*)d_in[13];
    const float* W_pd  = (const float*)d_in[14];
    const float* b_pd  = (const float*)d_in[15];
    const float* W_q   = (const float*)d_in[16];
    const float* b_q   = (const float*)d_in[17];
    const float* W_att = (const float*)d_in[18];

    const int dyn_smem = (Hz * Hz) * (int)sizeof(float) + 8 * 128 * 16;  // 64K + 16K
    static int attr_set = 0;
    if (!attr_set) {
        cudaFuncSetAttribute(persist_kernel,
                             cudaFuncAttributeMaxDynamicSharedMemorySize, dyn_smem);
        attr_set = 1;
    }

    coef_kernel<<<640, 128>>>(W_ref, W_s, b_s, b_ref, W_pd, W_d, b_d, b_pd,
                              W_ih, W_dec, b_dec, b_ih, b_hh);
    persist_kernel<<<NB, NT, dyn_smem>>>(st, dyn, W_hh, W_q, b_q, W_att,
                                         (float*)d_out, out_size);
}